// round 8
// baseline (speedup 1.0000x reference)
#include <cuda_runtime.h>
#include <cuda_bf16.h>
#include <math.h>
#include <string.h>
#include <stdint.h>

// ---------------------------------------------------------------------------
// Problem constants
// ---------------------------------------------------------------------------
#define BB 8
#define CC 128
#define HH 64
#define WW 64
#define UU 8
#define TOPK 2
#define LL 10
#define HID 128

#define HW (HH*WW)                       // 4096
#define N_FINAL (BB*CC*HW)               // 4194304
#define OFF_CLS  (N_FINAL)               // 80 floats
#define OFF_L2   (N_FINAL + 80)          // 1
#define OFF_TOPI (N_FINAL + 81)          // 16
#define OFF_LB   (N_FINAL + 97)          // 1

// ---------------------------------------------------------------------------
// Device scratch (static: allocations forbidden)
// ---------------------------------------------------------------------------
__device__ float g_pool[BB*CC];
__device__ float g_norms[12];
__device__ int   g_topi[BB*2];
__device__ float g_gate[BB*UU];
__device__ float g_part[256];                 // partial sums of P per (jb,slab)
__device__ float g_P[2*BB*CC*HW];             // 33.5 MB: per-active-unit conv outputs
                                              // layout: [j][b][co][hw]

// TF32 rounding (round-to-nearest-even onto 10-bit mantissa)
__device__ __forceinline__ float tf32r(float v)
{
    uint32_t r;
    asm("cvt.rna.tf32.f32 %0, %1;" : "=r"(r) : "f"(v));
    float f;
    asm("mov.b32 %0, %1;" : "=f"(f) : "r"(r));
    return f;
}

// ---------------------------------------------------------------------------
// K1: pooled[b,c] = mean_{h,w} x[b,c,h,w]
// ---------------------------------------------------------------------------
__global__ void k_pool(const float* __restrict__ x)
{
    int bc = blockIdx.x;                 // b*128 + c
    int t  = threadIdx.x;                // 256
    const float4* p = (const float4*)(x + (size_t)bc * HW);
    float s = 0.f;
    for (int i = t; i < 1024; i += 256) {
        float4 v = p[i];
        s += v.x + v.y + v.z + v.w;
    }
    #pragma unroll
    for (int off = 16; off; off >>= 1) s += __shfl_down_sync(0xffffffffu, s, off);
    __shared__ float ws[8];
    if ((t & 31) == 0) ws[t >> 5] = s;
    __syncthreads();
    if (t == 0) {
        float tot = 0.f;
        for (int w = 0; w < 8; ++w) tot += ws[w];
        g_pool[bc] = tot * (1.0f/4096.0f);
    }
}

// ---------------------------------------------------------------------------
// K2: Frobenius norms of the 12 router params
// ---------------------------------------------------------------------------
struct L2Args { const float* p[12]; int n[12]; };

__global__ void k_l2(L2Args a)
{
    int bi = blockIdx.x, t = threadIdx.x;       // 256 threads
    const float* p = a.p[bi]; int n = a.n[bi];
    float s = 0.f;
    for (int i = t; i < n; i += 256) { float v = p[i]; s += v*v; }
    #pragma unroll
    for (int off = 16; off; off >>= 1) s += __shfl_down_sync(0xffffffffu, s, off);
    __shared__ float ws[8];
    if ((t & 31) == 0) ws[t >> 5] = s;
    __syncthreads();
    if (t == 0) {
        float tot = 0.f;
        for (int w = 0; w < 8; ++w) tot += ws[w];
        g_norms[bi] = sqrtf(tot);
    }
}

// ---------------------------------------------------------------------------
// K3: router MLP + noise + top-2 + cls_logits + lb_loss + l2 (1 block, 128 thr)
// ---------------------------------------------------------------------------
struct Noise64 { float v[64]; };

__global__ void k_router(const float* __restrict__ W1, const float* __restrict__ b1,
                         const float* __restrict__ W2, const float* __restrict__ b2,
                         const float* __restrict__ W3, const float* __restrict__ b3,
                         const float* __restrict__ W4, const float* __restrict__ b4,
                         const float* __restrict__ Wu, const float* __restrict__ bu,
                         const float* __restrict__ Wc, const float* __restrict__ bc,
                         Noise64 nz, float* __restrict__ out)
{
    __shared__ float A[BB][HID];
    __shared__ float Bv[BB][HID];
    __shared__ float F[BB][64];
    __shared__ float S[BB][UU];
    __shared__ int   TI[BB][2];

    int t = threadIdx.x;   // 128

    // pooled
    for (int b = 0; b < BB; ++b) A[b][t] = g_pool[b*CC + t];
    __syncthreads();

    // L1
    {
        float acc[BB];
        float bb = b1[t];
        #pragma unroll
        for (int b = 0; b < BB; ++b) acc[b] = bb;
        for (int c = 0; c < HID; ++c) {
            float w = W1[t*HID + c];
            #pragma unroll
            for (int b = 0; b < BB; ++b) acc[b] = fmaf(A[b][c], w, acc[b]);
        }
        #pragma unroll
        for (int b = 0; b < BB; ++b) Bv[b][t] = fmaxf(acc[b], 0.f);
    }
    __syncthreads();

    // L2
    {
        float acc[BB];
        float bb = b2[t];
        #pragma unroll
        for (int b = 0; b < BB; ++b) acc[b] = bb;
        for (int c = 0; c < HID; ++c) {
            float w = W2[t*HID + c];
            #pragma unroll
            for (int b = 0; b < BB; ++b) acc[b] = fmaf(Bv[b][c], w, acc[b]);
        }
        #pragma unroll
        for (int b = 0; b < BB; ++b) A[b][t] = fmaxf(acc[b], 0.f);
    }
    __syncthreads();

    // L3: 128 -> 64
    if (t < 64) {
        float acc[BB];
        float bb = b3[t];
        #pragma unroll
        for (int b = 0; b < BB; ++b) acc[b] = bb;
        for (int c = 0; c < HID; ++c) {
            float w = W3[t*HID + c];
            #pragma unroll
            for (int b = 0; b < BB; ++b) acc[b] = fmaf(A[b][c], w, acc[b]);
        }
        #pragma unroll
        for (int b = 0; b < BB; ++b) Bv[b][t] = fmaxf(acc[b], 0.f);
    }
    __syncthreads();

    // L4: 64 -> 64, no relu
    if (t < 64) {
        float acc[BB];
        float bb = b4[t];
        #pragma unroll
        for (int b = 0; b < BB; ++b) acc[b] = bb;
        for (int c = 0; c < 64; ++c) {
            float w = W4[t*64 + c];
            #pragma unroll
            for (int b = 0; b < BB; ++b) acc[b] = fmaf(Bv[b][c], w, acc[b]);
        }
        #pragma unroll
        for (int b = 0; b < BB; ++b) F[b][t] = acc[b];
    }
    __syncthreads();

    // unit scores + noise
    if (t < BB*UU) {
        int b = t >> 3, u = t & 7;
        float a = bu[u] + nz.v[t];
        for (int c = 0; c < 64; ++c) a = fmaf(F[b][c], Wu[u*64 + c], a);
        S[b][u] = a;
    }
    // cls_logits
    if (t < BB*LL) {
        int b = t / LL, l = t % LL;
        float a = bc[l];
        for (int c = 0; c < 64; ++c) a = fmaf(F[b][c], Wc[l*64 + c], a);
        out[OFF_CLS + t] = a;
    }
    __syncthreads();

    // top-2
    if (t < BB) {
        int b = t;
        int i0 = 0; float v0 = S[b][0];
        for (int u = 1; u < UU; ++u) if (S[b][u] > v0) { v0 = S[b][u]; i0 = u; }
        int i1 = -1; float v1 = -3.4e38f;
        for (int u = 0; u < UU; ++u) if (u != i0 && S[b][u] > v1) { v1 = S[b][u]; i1 = u; }
        TI[b][0] = i0;  TI[b][1] = i1;
        g_topi[b*2] = i0;  g_topi[b*2+1] = i1;
        out[OFF_TOPI + b*2]     = (float)i0;
        out[OFF_TOPI + b*2 + 1] = (float)i1;
    }
    __syncthreads();

    if (t == 0) {
        int cnt[UU] = {0,0,0,0,0,0,0,0};
        for (int b = 0; b < BB; ++b) { cnt[TI[b][0]]++; cnt[TI[b][1]]++; }
        float lb = 0.f;
        for (int u = 0; u < UU; ++u) {
            float d = (float)cnt[u] * (1.0f/16.0f) - 0.125f;
            lb += d*d;
        }
        out[OFF_LB] = lb * (1.0f/8.0f);
        float s = 0.f;
        for (int i = 0; i < 12; ++i) s += g_norms[i];
        out[OFF_L2] = 0.01f * s;
    }
}

// ---------------------------------------------------------------------------
// K4: P[j][b] = conv3x3(x[b], conv_w[u_j])  (NO bias), TF32 operand rounding
// grid 1024 = 2 j x 8 b x 4 co-tiles x 16 spatial; 256 thr
// ---------------------------------------------------------------------------
__global__ void __launch_bounds__(256) k_conv(const float* __restrict__ xg,
                                              const float* __restrict__ conv_w)
{
    __shared__ float x_s[2800];       // 8 ci x 10 rows x (stride 35), cols 0..33
    __shared__ float w_s[2304];       // 32 co x 8 ci x 9

    int bid = blockIdx.x;
    int j   = bid >> 9;
    int r9  = bid & 511;
    int b   = r9 >> 6;
    int rem = r9 & 63;
    int co0 = (rem >> 4) * 32;
    int sp  = rem & 15;
    int gy0 = (sp >> 1) * 8;
    int gx0 = (sp & 1) * 32;

    int u = g_topi[b*2 + j];          // uniform per block

    int t   = threadIdx.x;
    int cog = t >> 5;                 // 0..7 : owns co0 + cog*4 .. +3
    int pg  = t & 31;
    int r   = pg >> 2;                // 0..7 output row in tile
    int cs  = (pg & 3) * 8;           // col segment start (8 px)

    float acc[4][8];
    #pragma unroll
    for (int c4 = 0; c4 < 4; ++c4)
        #pragma unroll
        for (int p = 0; p < 8; ++p) acc[c4][p] = 0.f;

    #pragma unroll 1
    for (int cc = 0; cc < 16; ++cc) {
        __syncthreads();
        // input tile: 8 ci x 10 rows x 34 cols (zero-padded), TF32-rounded
        for (int li = t; li < 2720; li += 256) {
            int ci  = li / 340;
            int rm  = li - ci * 340;
            int ry  = rm / 34;
            int rx  = rm - ry * 34;
            int gy  = gy0 - 1 + ry;
            int gx  = gx0 - 1 + rx;
            float v = 0.f;
            if ((unsigned)gy < 64u && (unsigned)gx < 64u)
                v = xg[((size_t)(b*CC + cc*8 + ci) * 64 + gy) * 64 + gx];
            x_s[ci*350 + ry*35 + rx] = tf32r(v);
        }
        // weight tile from conv_w[u], TF32-rounded
        for (int li = t; li < 2304; li += 256) {
            int co = li / 72;
            int rm = li - co * 72;
            w_s[li] = tf32r(conv_w[(size_t)(u*CC + co0 + co) * (CC*9) + cc*72 + rm]);
        }
        __syncthreads();

        #pragma unroll 1
        for (int ci = 0; ci < 8; ++ci) {
            const float* xrow = &x_s[ci*350 + cs];
            const float* wrow = &w_s[cog*4*72 + ci*9];
            #pragma unroll
            for (int dy = 0; dy < 3; ++dy) {
                float xv[10];
                #pragma unroll
                for (int i = 0; i < 10; ++i) xv[i] = xrow[(r + dy) * 35 + i];
                #pragma unroll
                for (int dx = 0; dx < 3; ++dx) {
                    #pragma unroll
                    for (int c4 = 0; c4 < 4; ++c4) {
                        float wv = wrow[c4*72 + dy*3 + dx];
                        #pragma unroll
                        for (int p = 0; p < 8; ++p)
                            acc[c4][p] = fmaf(wv, xv[p + dx], acc[c4][p]);
                    }
                }
            }
        }
    }

    // epilogue -> g_P, layout [j][b][co][hw]
    #pragma unroll
    for (int c4 = 0; c4 < 4; ++c4) {
        int co = co0 + cog*4 + c4;
        size_t obase = ((size_t)((j*BB + b)*CC + co) * 64 + (gy0 + r)) * 64 + gx0 + cs;
        #pragma unroll
        for (int p = 0; p < 8; ++p)
            g_P[obase + p] = acc[c4][p];
    }
}

// ---------------------------------------------------------------------------
// K5: partial sums of P. Linear first-dim index jb = j*8+b ([j][b] layout).
// 256 blocks = 16 jb x 16 slabs
// ---------------------------------------------------------------------------
__global__ void k_sum()
{
    int bid  = blockIdx.x;
    int jb   = bid >> 4;         // j*8 + b  (matches g_P layout)
    int slab = bid & 15;
    int t    = threadIdx.x;      // 256
    const float4* p = (const float4*)(g_P + (size_t)jb * (CC*HW) + slab * 32768);
    float s = 0.f;
    for (int i = t; i < 8192; i += 256) {
        float4 v = p[i];
        s += v.x + v.y + v.z + v.w;
    }
    #pragma unroll
    for (int off = 16; off; off >>= 1) s += __shfl_down_sync(0xffffffffu, s, off);
    __shared__ float ws[8];
    if ((t & 31) == 0) ws[t >> 5] = s;
    __syncthreads();
    if (t == 0) {
        float tot = 0.f;
        for (int w = 0; w < 8; ++w) tot += ws[w];
        g_part[bid] = tot;       // g_part[(j*8+b)*16 + slab]
    }
}

// ---------------------------------------------------------------------------
// K6: gates = softmax over unit means (1 block, 64 thr)
//   inactive u: mean = bsum[u]/128
//   active  u: mean = (Psum + 4096*bsum[u]) / 524288
// *** FIXED: g_part indexed with jb = j*8+b, matching g_P/k_sum layout ***
// ---------------------------------------------------------------------------
__global__ void k_gates(const float* __restrict__ conv_b)
{
    __shared__ float bsum[UU];
    __shared__ float m[BB][UU];
    int t = threadIdx.x;   // 64

    if (t < UU) {
        float s = 0.f;
        for (int c = 0; c < CC; ++c) s += conv_b[t*CC + c];
        bsum[t] = s;
    }
    __syncthreads();
    if (t < BB*UU) {
        int b = t >> 3, u = t & 7;
        m[b][u] = bsum[u] * (1.0f/128.0f);
    }
    __syncthreads();
    if (t < BB*2) {
        int b = t >> 1, j = t & 1;
        int u = g_topi[b*2 + j];
        int jb = j*BB + b;                       // <-- the fix
        float ps = 0.f;
        for (int s = 0; s < 16; ++s) ps += g_part[jb*16 + s];
        m[b][u] = (ps + 4096.0f * bsum[u]) * (1.0f/524288.0f);
    }
    __syncthreads();
    if (t < BB) {
        int b = t;
        float mx = -3.4e38f;
        for (int u = 0; u < UU; ++u) mx = fmaxf(mx, m[b][u]);
        float e[UU], s = 0.f;
        for (int u = 0; u < UU; ++u) { e[u] = expf(m[b][u] - mx); s += e[u]; }
        for (int u = 0; u < UU; ++u) g_gate[b*UU + u] = e[u] / s;
    }
}

// ---------------------------------------------------------------------------
// K7: final = g0*P0 + g1*P1 + beff   grid 1024 = (b,co), 256 thr
// ---------------------------------------------------------------------------
__global__ void k_combine(const float* __restrict__ conv_b, float* __restrict__ out)
{
    int bid = blockIdx.x;
    int b  = bid >> 7;
    int co = bid & 127;
    int t  = threadIdx.x;   // 256
    __shared__ float sh[3];
    if (t == 0) {
        int u0 = g_topi[b*2], u1 = g_topi[b*2+1];
        float be = 0.f;
        for (int u = 0; u < UU; ++u) be += g_gate[b*UU + u] * conv_b[u*CC + co];
        sh[0] = g_gate[b*UU + u0];
        sh[1] = g_gate[b*UU + u1];
        sh[2] = be;
    }
    __syncthreads();
    float g0 = sh[0], g1 = sh[1], be = sh[2];
    const float4* p0 = (const float4*)(g_P + (size_t)((0*BB + b)*CC + co) * HW);
    const float4* p1 = (const float4*)(g_P + (size_t)((1*BB + b)*CC + co) * HW);
    float4* o = (float4*)(out + (size_t)(b*CC + co) * HW);
    for (int i = t; i < 1024; i += 256) {
        float4 a = p0[i], c = p1[i], r;
        r.x = g0*a.x + g1*c.x + be;
        r.y = g0*a.y + g1*c.y + be;
        r.z = g0*a.z + g1*c.z + be;
        r.w = g0*a.w + g1*c.w + be;
        o[i] = r;
    }
}

// ---------------------------------------------------------------------------
// Host: JAX threefry2x32 noise for key(42), shape (8,8)
// PARTITIONABLE mode: bits[i] = xor-fold of threefry2x32(key, (0, i))
// ---------------------------------------------------------------------------
static inline uint32_t rotl32(uint32_t x, int d) { return (x << d) | (x >> (32 - d)); }

static void threefry2x32_host(uint32_t k0, uint32_t k1, uint32_t x0, uint32_t x1,
                              uint32_t* o0, uint32_t* o1)
{
    const uint32_t ks0 = k0, ks1 = k1, ks2 = k0 ^ k1 ^ 0x1BD11BDAu;
    const int ra[4] = {13, 15, 26, 6};
    const int rb[4] = {17, 29, 16, 24};
    x0 += ks0; x1 += ks1;
    for (int i = 0; i < 4; ++i) { x0 += x1; x1 = rotl32(x1, ra[i]); x1 ^= x0; }
    x0 += ks1; x1 += ks2 + 1u;
    for (int i = 0; i < 4; ++i) { x0 += x1; x1 = rotl32(x1, rb[i]); x1 ^= x0; }
    x0 += ks2; x1 += ks0 + 2u;
    for (int i = 0; i < 4; ++i) { x0 += x1; x1 = rotl32(x1, ra[i]); x1 ^= x0; }
    x0 += ks0; x1 += ks1 + 3u;
    for (int i = 0; i < 4; ++i) { x0 += x1; x1 = rotl32(x1, rb[i]); x1 ^= x0; }
    x0 += ks1; x1 += ks2 + 4u;
    for (int i = 0; i < 4; ++i) { x0 += x1; x1 = rotl32(x1, ra[i]); x1 ^= x0; }
    x0 += ks2; x1 += ks0 + 5u;
    *o0 = x0; *o1 = x1;
}

static double erfinv_host(double x)
{
    double p;
    double ww = -log((1.0 - x) * (1.0 + x));
    if (ww < 5.0) {
        ww -= 2.5;
        p = 2.81022636e-08;        p = 3.43273939e-07 + p*ww;
        p = -3.5233877e-06 + p*ww; p = -4.39150654e-06 + p*ww;
        p = 0.00021858087 + p*ww;  p = -0.00125372503 + p*ww;
        p = -0.00417768164 + p*ww; p = 0.246640727 + p*ww;
        p = 1.50140941 + p*ww;
    } else {
        ww = sqrt(ww) - 3.0;
        p = -0.000200214257;       p = 0.000100950558 + p*ww;
        p = 0.00134934322 + p*ww;  p = -0.00367342844 + p*ww;
        p = 0.00573950773 + p*ww;  p = -0.0076224613 + p*ww;
        p = 0.00943887047 + p*ww;  p = 1.00167406 + p*ww;
        p = 2.83297682 + p*ww;
    }
    return p * x;   // XLA f32 ErfInv: pure polynomial, no Newton refinement
}

static void compute_noise(float* noise /*64*/)
{
    float lo = nextafterf(-1.0f, 0.0f);
    float range = 1.0f - lo;    // rounds to 2.0f (round-to-even tie), matching XLA
    for (uint32_t i = 0; i < 64; ++i) {
        uint32_t o0, o1;
        threefry2x32_host(0u, 42u, 0u, i, &o0, &o1);
        uint32_t bits = o0 ^ o1;
        uint32_t fb = (bits >> 9) | 0x3f800000u;
        float f; memcpy(&f, &fb, 4);
        f -= 1.0f;
        float u = f * range + lo;
        if (u < lo) u = lo;
        double z = erfinv_host((double)u);
        noise[i] = (float)(sqrt(2.0) * z) * 0.01f;
    }
}

// ---------------------------------------------------------------------------
// Entry — inputs resolved BY SIZE (robust to metadata permutations)
// ---------------------------------------------------------------------------
static const float* find_by_size(void* const* d_in, const int* in_sizes, int n_in,
                                 int want, int occurrence)
{
    int seen = 0;
    for (int i = 0; i < n_in; ++i) {
        if (in_sizes[i] == want) {
            if (seen == occurrence) return (const float*)d_in[i];
            ++seen;
        }
    }
    return nullptr;
}

extern "C" void kernel_launch(void* const* d_in, const int* in_sizes, int n_in,
                              void* d_out, int out_size)
{
    const float* x      = find_by_size(d_in, in_sizes, n_in, BB*CC*HW, 0);      // 4194304
    const float* W1     = find_by_size(d_in, in_sizes, n_in, 16384, 0);
    const float* W2     = find_by_size(d_in, in_sizes, n_in, 16384, 1);
    const float* b1     = find_by_size(d_in, in_sizes, n_in, 128, 0);
    const float* b2     = find_by_size(d_in, in_sizes, n_in, 128, 1);
    const float* W3     = find_by_size(d_in, in_sizes, n_in, 8192, 0);
    const float* b3     = find_by_size(d_in, in_sizes, n_in, 64, 0);
    const float* W4     = find_by_size(d_in, in_sizes, n_in, 4096, 0);
    const float* b4     = find_by_size(d_in, in_sizes, n_in, 64, 1);
    const float* Wu     = find_by_size(d_in, in_sizes, n_in, 512, 0);
    const float* bu     = find_by_size(d_in, in_sizes, n_in, 8, 0);
    const float* Wc     = find_by_size(d_in, in_sizes, n_in, 640, 0);
    const float* bc     = find_by_size(d_in, in_sizes, n_in, 10, 0);
    const float* conv_w = find_by_size(d_in, in_sizes, n_in, UU*CC*CC*9, 0);    // 1179648
    const float* conv_b = find_by_size(d_in, in_sizes, n_in, 1024, 0);
    float* out = (float*)d_out;

    if (!x || !W1 || !W2 || !b1 || !b2 || !W3 || !b3 || !W4 || !b4 ||
        !Wu || !bu || !Wc || !bc || !conv_w || !conv_b) {
        x = (const float*)d_in[0];
        W1 = (const float*)d_in[1];  b1 = (const float*)d_in[2];
        W2 = (const float*)d_in[3];  b2 = (const float*)d_in[4];
        W3 = (const float*)d_in[5];  b3 = (const float*)d_in[6];
        W4 = (const float*)d_in[7];  b4 = (const float*)d_in[8];
        Wu = (const float*)d_in[9];  bu = (const float*)d_in[10];
        Wc = (const float*)d_in[11]; bc = (const float*)d_in[12];
        conv_w = (const float*)d_in[13]; conv_b = (const float*)d_in[14];
    }

    Noise64 nz;
    compute_noise(nz.v);

    L2Args la;
    const float* l2p[12] = {W1,b1,W2,b2,W3,b3,W4,b4,Wu,bu,Wc,bc};
    const int    l2n[12] = {16384,128,16384,128,8192,64,4096,64,512,8,640,10};
    for (int i = 0; i < 12; ++i) { la.p[i] = l2p[i]; la.n[i] = l2n[i]; }

    k_pool<<<BB*CC, 256>>>(x);
    k_l2<<<12, 256>>>(la);
    k_router<<<1, 128>>>(W1, b1, W2, b2, W3, b3, W4, b4,
                         Wu, bu, Wc, bc, nz, out);
    k_conv<<<1024, 256>>>(x, conv_w);
    k_sum<<<256, 256>>>();
    k_gates<<<1, 64>>>(conv_b);
    k_combine<<<1024, 256>>>(conv_b, out);
}

// round 10
// speedup vs baseline: 1.3484x; 1.3484x over previous
#include <cuda_runtime.h>
#include <cuda_bf16.h>
#include <math.h>
#include <string.h>
#include <stdint.h>

// ---------------------------------------------------------------------------
// Problem constants
// ---------------------------------------------------------------------------
#define BB 8
#define CC 128
#define HH 64
#define WW 64
#define UU 8
#define TOPK 2
#define LL 10
#define HID 128

#define HW (HH*WW)                       // 4096
#define N_FINAL (BB*CC*HW)               // 4194304
#define OFF_CLS  (N_FINAL)               // 80 floats
#define OFF_L2   (N_FINAL + 80)          // 1
#define OFF_TOPI (N_FINAL + 81)          // 16
#define OFF_LB   (N_FINAL + 97)          // 1

// ---------------------------------------------------------------------------
// Device scratch (static: allocations forbidden)
// ---------------------------------------------------------------------------
__device__ float g_stats[BB*CC*9];   // per (b,ci): T,R0,R63,C0,C63,x00,x0_63,x63_0,x63_63
__device__ float g_wsum[UU*CC*9];    // sum over co of conv_w[u,co,ci,k]
__device__ float g_norms[12];
__device__ int   g_topi[BB*2];
__device__ float g_gate[BB*UU];
__device__ float g_beff[BB*CC];
__device__ float g_Weff[BB*CC*CC*9]; // 4.72 MB [b][co][ci*9+k], per-unit tf32-rounded then gated

// TF32 rounding (round-to-nearest-even onto 10-bit mantissa)
__device__ __forceinline__ float tf32r(float v)
{
    uint32_t r;
    asm("cvt.rna.tf32.f32 %0, %1;" : "=r"(r) : "f"(v));
    float f;
    asm("mov.b32 %0, %1;" : "=f"(f) : "r"(r));
    return f;
}

// packed fp32x2 fma: d = a*b + d (elementwise on 2 packed floats)
__device__ __forceinline__ void ffma2(unsigned long long& d,
                                      unsigned long long a,
                                      unsigned long long b)
{
    asm("fma.rn.f32x2 %0, %1, %2, %3;" : "=l"(d) : "l"(a), "l"(b), "l"(d));
}

__device__ __forceinline__ float2 unpack2(unsigned long long v)
{
    float2 f;
    asm("mov.b64 {%0,%1}, %2;" : "=f"(f.x), "=f"(f.y) : "l"(v));
    return f;
}

// ---------------------------------------------------------------------------
// K1: per-(b,ci) spatial stats (T also serves as pooled*4096)
// ---------------------------------------------------------------------------
__global__ void k_stats(const float* __restrict__ x)
{
    int bc = blockIdx.x;           // b*128+ci
    int t  = threadIdx.x;          // 128
    const float* base = x + (size_t)bc * HW;

    float T=0.f, r0=0.f, r63=0.f, c0=0.f, c63=0.f;
    for (int i = t; i < HW; i += 128) {
        float v = base[i];
        int y = i >> 6, xc = i & 63;
        T += v;
        if (y == 0)   r0  += v;
        if (y == 63)  r63 += v;
        if (xc == 0)  c0  += v;
        if (xc == 63) c63 += v;
    }
    #pragma unroll
    for (int off = 16; off; off >>= 1) {
        T   += __shfl_down_sync(0xffffffffu, T,   off);
        r0  += __shfl_down_sync(0xffffffffu, r0,  off);
        r63 += __shfl_down_sync(0xffffffffu, r63, off);
        c0  += __shfl_down_sync(0xffffffffu, c0,  off);
        c63 += __shfl_down_sync(0xffffffffu, c63, off);
    }
    __shared__ float red[4][5];
    if ((t & 31) == 0) {
        int w = t >> 5;
        red[w][0]=T; red[w][1]=r0; red[w][2]=r63; red[w][3]=c0; red[w][4]=c63;
    }
    __syncthreads();
    if (t == 0) {
        float s[5] = {0,0,0,0,0};
        for (int w = 0; w < 4; ++w)
            for (int k = 0; k < 5; ++k) s[k] += red[w][k];
        float* o = g_stats + (size_t)bc * 9;
        o[0]=s[0]; o[1]=s[1]; o[2]=s[2]; o[3]=s[3]; o[4]=s[4];
        o[5]=base[0];
        o[6]=base[63];
        o[7]=base[63*64];
        o[8]=base[HW-1];
    }
}

// ---------------------------------------------------------------------------
// K2: wsum[u,ci,k] = sum_co conv_w[u,co,ci,k]
// ---------------------------------------------------------------------------
__global__ void k_wsum(const float* __restrict__ conv_w)
{
    int u   = blockIdx.x;
    int idx = blockIdx.y * 288 + threadIdx.x;   // 0..1151
    const float* base = conv_w + (size_t)u * CC * (CC*9) + idx;
    float s = 0.f;
    for (int co = 0; co < CC; ++co) s += base[(size_t)co * (CC*9)];
    g_wsum[u * (CC*9) + idx] = s;
}

// ---------------------------------------------------------------------------
// K3: Frobenius norms of the 12 router params
// ---------------------------------------------------------------------------
struct L2Args { const float* p[12]; int n[12]; };

__global__ void k_l2(L2Args a)
{
    int bi = blockIdx.x, t = threadIdx.x;       // 256
    const float* p = a.p[bi]; int n = a.n[bi];
    float s = 0.f;
    for (int i = t; i < n; i += 256) { float v = p[i]; s += v*v; }
    #pragma unroll
    for (int off = 16; off; off >>= 1) s += __shfl_down_sync(0xffffffffu, s, off);
    __shared__ float ws[8];
    if ((t & 31) == 0) ws[t >> 5] = s;
    __syncthreads();
    if (t == 0) {
        float tot = 0.f;
        for (int w = 0; w < 8; ++w) tot += ws[w];
        g_norms[bi] = sqrtf(tot);
    }
}

// ---------------------------------------------------------------------------
// K4: router MLP + noise + top-2 + cls + lb + l2 + ANALYTIC gates (1 blk,128)
// ---------------------------------------------------------------------------
struct Noise64 { float v[64]; };

__global__ void k_router(const float* __restrict__ W1, const float* __restrict__ b1,
                         const float* __restrict__ W2, const float* __restrict__ b2,
                         const float* __restrict__ W3, const float* __restrict__ b3,
                         const float* __restrict__ W4, const float* __restrict__ b4,
                         const float* __restrict__ Wu, const float* __restrict__ bu,
                         const float* __restrict__ Wc, const float* __restrict__ bc,
                         const float* __restrict__ conv_b,
                         Noise64 nz, float* __restrict__ out)
{
    __shared__ float A[BB][HID];
    __shared__ float Bv[BB][HID];
    __shared__ float F[BB][64];
    __shared__ float S[BB][UU];
    __shared__ int   TI[BB][2];
    __shared__ float bsum_s[UU];
    __shared__ float m_s[BB][UU];
    __shared__ float S_s[CC*9];
    __shared__ float red[128];

    int t = threadIdx.x;   // 128

    // pooled from stats T
    for (int b = 0; b < BB; ++b)
        A[b][t] = g_stats[(size_t)(b*CC + t) * 9] * (1.0f/4096.0f);
    __syncthreads();

    // L1
    {
        float acc[BB]; float bb = b1[t];
        #pragma unroll
        for (int b = 0; b < BB; ++b) acc[b] = bb;
        for (int c = 0; c < HID; ++c) {
            float w = W1[t*HID + c];
            #pragma unroll
            for (int b = 0; b < BB; ++b) acc[b] = fmaf(A[b][c], w, acc[b]);
        }
        #pragma unroll
        for (int b = 0; b < BB; ++b) Bv[b][t] = fmaxf(acc[b], 0.f);
    }
    __syncthreads();
    // L2
    {
        float acc[BB]; float bb = b2[t];
        #pragma unroll
        for (int b = 0; b < BB; ++b) acc[b] = bb;
        for (int c = 0; c < HID; ++c) {
            float w = W2[t*HID + c];
            #pragma unroll
            for (int b = 0; b < BB; ++b) acc[b] = fmaf(Bv[b][c], w, acc[b]);
        }
        #pragma unroll
        for (int b = 0; b < BB; ++b) A[b][t] = fmaxf(acc[b], 0.f);
    }
    __syncthreads();
    // L3: 128 -> 64
    if (t < 64) {
        float acc[BB]; float bb = b3[t];
        #pragma unroll
        for (int b = 0; b < BB; ++b) acc[b] = bb;
        for (int c = 0; c < HID; ++c) {
            float w = W3[t*HID + c];
            #pragma unroll
            for (int b = 0; b < BB; ++b) acc[b] = fmaf(A[b][c], w, acc[b]);
        }
        #pragma unroll
        for (int b = 0; b < BB; ++b) Bv[b][t] = fmaxf(acc[b], 0.f);
    }
    __syncthreads();
    // L4: 64 -> 64 (no relu)
    if (t < 64) {
        float acc[BB]; float bb = b4[t];
        #pragma unroll
        for (int b = 0; b < BB; ++b) acc[b] = bb;
        for (int c = 0; c < 64; ++c) {
            float w = W4[t*64 + c];
            #pragma unroll
            for (int b = 0; b < BB; ++b) acc[b] = fmaf(Bv[b][c], w, acc[b]);
        }
        #pragma unroll
        for (int b = 0; b < BB; ++b) F[b][t] = acc[b];
    }
    __syncthreads();

    // unit scores + noise
    if (t < BB*UU) {
        int b = t >> 3, u = t & 7;
        float a = bu[u] + nz.v[t];
        for (int c = 0; c < 64; ++c) a = fmaf(F[b][c], Wu[u*64 + c], a);
        S[b][u] = a;
    }
    // cls_logits
    if (t < BB*LL) {
        int b = t / LL, l = t % LL;
        float a = bc[l];
        for (int c = 0; c < 64; ++c) a = fmaf(F[b][c], Wc[l*64 + c], a);
        out[OFF_CLS + t] = a;
    }
    // per-unit bias sums
    if (t >= 64 && t < 64 + UU) {
        int u = t - 64;
        float s = 0.f;
        for (int c = 0; c < CC; ++c) s += conv_b[u*CC + c];
        bsum_s[u] = s;
    }
    __syncthreads();

    // top-2 (first occurrence wins on ties)
    if (t < BB) {
        int b = t;
        int i0 = 0; float v0 = S[b][0];
        for (int u = 1; u < UU; ++u) if (S[b][u] > v0) { v0 = S[b][u]; i0 = u; }
        int i1 = -1; float v1 = -3.4e38f;
        for (int u = 0; u < UU; ++u) if (u != i0 && S[b][u] > v1) { v1 = S[b][u]; i1 = u; }
        TI[b][0] = i0;  TI[b][1] = i1;
        g_topi[b*2] = i0;  g_topi[b*2+1] = i1;
        out[OFF_TOPI + b*2]     = (float)i0;
        out[OFF_TOPI + b*2 + 1] = (float)i1;
    }
    __syncthreads();

    if (t == 0) {
        int cnt[UU] = {0,0,0,0,0,0,0,0};
        for (int b = 0; b < BB; ++b) { cnt[TI[b][0]]++; cnt[TI[b][1]]++; }
        float lb = 0.f;
        for (int u = 0; u < UU; ++u) {
            float d = (float)cnt[u] * (1.0f/16.0f) - 0.125f;
            lb += d*d;
        }
        out[OFF_LB] = lb * (1.0f/8.0f);
        float s = 0.f;
        for (int i = 0; i < 12; ++i) s += g_norms[i];
        out[OFF_L2] = 0.01f * s;
    }

    // init unit means with bias-only term (inactive units)
    if (t < BB*UU) m_s[t>>3][t&7] = bsum_s[t&7] * (1.0f/128.0f);
    __syncthreads();

    // active-unit means via analytic conv window sums (inclusion-exclusion)
    for (int b = 0; b < BB; ++b) {
        {
            const float* st = g_stats + (size_t)(b*CC + t) * 9;
            float T  = st[0], R0 = st[1], R63 = st[2], C0 = st[3], C63 = st[4];
            float x00 = st[5], x0e = st[6], xe0 = st[7], xee = st[8];
            #pragma unroll
            for (int dy = 0; dy < 3; ++dy)
                #pragma unroll
                for (int dx = 0; dx < 3; ++dx) {
                    float s = T;
                    if (dy == 0) s -= R63;
                    if (dy == 2) s -= R0;
                    if (dx == 0) s -= C63;
                    if (dx == 2) s -= C0;
                    if (dy == 0 && dx == 0) s += xee;
                    if (dy == 0 && dx == 2) s += xe0;
                    if (dy == 2 && dx == 0) s += x0e;
                    if (dy == 2 && dx == 2) s += x00;
                    S_s[t*9 + dy*3 + dx] = s;
                }
        }
        __syncthreads();
        for (int j = 0; j < 2; ++j) {
            int u = TI[b][j];
            const float* wr = g_wsum + (size_t)u * (CC*9) + t*9;
            const float* sr = S_s + t*9;
            float part = 0.f;
            #pragma unroll
            for (int k = 0; k < 9; ++k) part += wr[k] * sr[k];
            red[t] = part;
            __syncthreads();
            for (int off = 64; off; off >>= 1) {
                if (t < off) red[t] += red[t + off];
                __syncthreads();
            }
            if (t == 0) m_s[b][u] += red[0] * (1.0f/524288.0f);
            __syncthreads();
        }
    }

    // softmax -> gates
    if (t < BB) {
        int b = t;
        float mx = -3.4e38f;
        for (int u = 0; u < UU; ++u) mx = fmaxf(mx, m_s[b][u]);
        float e[UU], s = 0.f;
        for (int u = 0; u < UU; ++u) { e[u] = expf(m_s[b][u] - mx); s += e[u]; }
        for (int u = 0; u < UU; ++u) g_gate[b*UU + u] = e[u] / s;
    }
}

// ---------------------------------------------------------------------------
// K5: W_eff[b,co] = g0*tf32(w[u0,co]) + g1*tf32(w[u1,co]);  b_eff
// ---------------------------------------------------------------------------
__global__ void k_weff(const float* __restrict__ conv_w, const float* __restrict__ conv_b)
{
    int b  = blockIdx.x >> 7;
    int co = blockIdx.x & 127;
    int t  = threadIdx.x;          // 128
    int u0 = g_topi[b*2], u1 = g_topi[b*2+1];
    float g0 = g_gate[b*UU + u0], g1 = g_gate[b*UU + u1];
    const float* w0 = conv_w + (size_t)(u0*CC + co) * (CC*9);
    const float* w1 = conv_w + (size_t)(u1*CC + co) * (CC*9);
    float* dst = g_Weff + (size_t)(b*CC + co) * (CC*9);
    for (int i = t; i < CC*9; i += 128)
        dst[i] = g0 * tf32r(w0[i]) + g1 * tf32r(w1[i]);
    if (t == 0) {
        float s = 0.f;
        for (int u = 0; u < UU; ++u) s += g_gate[b*UU + u] * conv_b[u*CC + co];
        g_beff[b*CC + co] = s;
    }
}

// ---------------------------------------------------------------------------
// K6: final[b] = conv3x3(tf32(x[b]), W_eff[b]) + b_eff  -> out directly
// grid 512 = 8 b x 4 co-tiles x 16 spatial; 256 thr; f32x2 packed FMA
// ---------------------------------------------------------------------------
__global__ void __launch_bounds__(256) k_conv(const float* __restrict__ xg,
                                              float* __restrict__ out)
{
    __shared__ __align__(16) float  x_s[8*10*36];    // 2880 floats, stride 36
    __shared__ __align__(16) float2 w2_s[2304];      // 32co x 8ci x 9, (w,w) pairs

    int bid = blockIdx.x;
    int b   = bid >> 6;
    int rem = bid & 63;
    int co0 = (rem >> 4) * 32;
    int sp  = rem & 15;
    int gy0 = (sp >> 1) * 8;
    int gx0 = (sp & 1) * 32;

    int t   = threadIdx.x;
    int cog = t >> 5;                 // warp id: owns co0+cog*4 .. +3
    int pg  = t & 31;
    int r   = pg >> 2;                // output row in tile (0..7)
    int cs  = (pg & 3) * 8;           // col segment start (even -> 8B aligned)

    unsigned long long acc2[4][4];
    #pragma unroll
    for (int c4 = 0; c4 < 4; ++c4)
        #pragma unroll
        for (int k = 0; k < 4; ++k) acc2[c4][k] = 0ull;

    #pragma unroll 1
    for (int cc = 0; cc < 16; ++cc) {
        __syncthreads();
        // input tile: 8 ci x 10 rows x 34 cols (zero-padded), TF32-rounded
        for (int li = t; li < 2720; li += 256) {
            int ci  = li / 340;
            int rm  = li - ci * 340;
            int ry  = rm / 34;
            int rx  = rm - ry * 34;
            int gy  = gy0 - 1 + ry;
            int gx  = gx0 - 1 + rx;
            float v = 0.f;
            if ((unsigned)gy < 64u && (unsigned)gx < 64u)
                v = xg[((size_t)(b*CC + cc*8 + ci) * 64 + gy) * 64 + gx];
            x_s[ci*360 + ry*36 + rx] = tf32r(v);
        }
        // weights as broadcast pairs
        for (int li = t; li < 2304; li += 256) {
            int co = li / 72;
            int rm = li - co * 72;
            float v = g_Weff[(size_t)(b*CC + co0 + co) * (CC*9) + cc*72 + rm];
            w2_s[li] = make_float2(v, v);
        }
        __syncthreads();

        #pragma unroll 1
        for (int ci = 0; ci < 8; ++ci) {
            const float* xbase = x_s + ci*360 + cs;
            const float2* wrow = w2_s + cog*4*72 + ci*9;
            #pragma unroll
            for (int dy = 0; dy < 3; ++dy) {
                const unsigned long long* xp =
                    (const unsigned long long*)(xbase + (r + dy) * 36);
                unsigned long long A0 = xp[0], A1 = xp[1], A2 = xp[2],
                                   A3 = xp[3], A4 = xp[4];
                unsigned long long B0 = (A0 >> 32) | (A1 << 32);
                unsigned long long B1 = (A1 >> 32) | (A2 << 32);
                unsigned long long B2 = (A2 >> 32) | (A3 << 32);
                unsigned long long B3 = (A3 >> 32) | (A4 << 32);
                #pragma unroll
                for (int c4 = 0; c4 < 4; ++c4) {
                    const unsigned long long* wp =
                        (const unsigned long long*)(wrow + c4*72 + dy*3);
                    unsigned long long w0 = wp[0], w1 = wp[1], w2 = wp[2];
                    // dx = 0 : aligned pairs A0..A3
                    ffma2(acc2[c4][0], A0, w0);
                    ffma2(acc2[c4][1], A1, w0);
                    ffma2(acc2[c4][2], A2, w0);
                    ffma2(acc2[c4][3], A3, w0);
                    // dx = 1 : shifted pairs B0..B3
                    ffma2(acc2[c4][0], B0, w1);
                    ffma2(acc2[c4][1], B1, w1);
                    ffma2(acc2[c4][2], B2, w1);
                    ffma2(acc2[c4][3], B3, w1);
                    // dx = 2 : aligned pairs A1..A4
                    ffma2(acc2[c4][0], A1, w2);
                    ffma2(acc2[c4][1], A2, w2);
                    ffma2(acc2[c4][2], A3, w2);
                    ffma2(acc2[c4][3], A4, w2);
                }
            }
        }
    }

    // epilogue: + b_eff, write directly to out
    #pragma unroll
    for (int c4 = 0; c4 < 4; ++c4) {
        int co = co0 + cog*4 + c4;
        float be = g_beff[b*CC + co];
        size_t obase = ((size_t)(b*CC + co) * 64 + (gy0 + r)) * 64 + gx0 + cs;
        float2 p0 = unpack2(acc2[c4][0]);
        float2 p1 = unpack2(acc2[c4][1]);
        float2 p2 = unpack2(acc2[c4][2]);
        float2 p3 = unpack2(acc2[c4][3]);
        float4 v0 = make_float4(p0.x + be, p0.y + be, p1.x + be, p1.y + be);
        float4 v1 = make_float4(p2.x + be, p2.y + be, p3.x + be, p3.y + be);
        *(float4*)(out + obase)     = v0;
        *(float4*)(out + obase + 4) = v1;
    }
}

// ---------------------------------------------------------------------------
// Host: JAX threefry2x32 noise for key(42), shape (8,8)
// PARTITIONABLE mode: bits[i] = xor-fold of threefry2x32(key, (0, i))
// ---------------------------------------------------------------------------
static inline uint32_t rotl32(uint32_t x, int d) { return (x << d) | (x >> (32 - d)); }

static void threefry2x32_host(uint32_t k0, uint32_t k1, uint32_t x0, uint32_t x1,
                              uint32_t* o0, uint32_t* o1)
{
    const uint32_t ks0 = k0, ks1 = k1, ks2 = k0 ^ k1 ^ 0x1BD11BDAu;
    const int ra[4] = {13, 15, 26, 6};
    const int rb[4] = {17, 29, 16, 24};
    x0 += ks0; x1 += ks1;
    for (int i = 0; i < 4; ++i) { x0 += x1; x1 = rotl32(x1, ra[i]); x1 ^= x0; }
    x0 += ks1; x1 += ks2 + 1u;
    for (int i = 0; i < 4; ++i) { x0 += x1; x1 = rotl32(x1, rb[i]); x1 ^= x0; }
    x0 += ks2; x1 += ks0 + 2u;
    for (int i = 0; i < 4; ++i) { x0 += x1; x1 = rotl32(x1, ra[i]); x1 ^= x0; }
    x0 += ks0; x1 += ks1 + 3u;
    for (int i = 0; i < 4; ++i) { x0 += x1; x1 = rotl32(x1, rb[i]); x1 ^= x0; }
    x0 += ks1; x1 += ks2 + 4u;
    for (int i = 0; i < 4; ++i) { x0 += x1; x1 = rotl32(x1, ra[i]); x1 ^= x0; }
    x0 += ks2; x1 += ks0 + 5u;
    *o0 = x0; *o1 = x1;
}

static double erfinv_host(double x)
{
    double p;
    double ww = -log((1.0 - x) * (1.0 + x));
    if (ww < 5.0) {
        ww -= 2.5;
        p = 2.81022636e-08;        p = 3.43273939e-07 + p*ww;
        p = -3.5233877e-06 + p*ww; p = -4.39150654e-06 + p*ww;
        p = 0.00021858087 + p*ww;  p = -0.00125372503 + p*ww;
        p = -0.00417768164 + p*ww; p = 0.246640727 + p*ww;
        p = 1.50140941 + p*ww;
    } else {
        ww = sqrt(ww) - 3.0;
        p = -0.000200214257;       p = 0.000100950558 + p*ww;
        p = 0.00134934322 + p*ww;  p = -0.00367342844 + p*ww;
        p = 0.00573950773 + p*ww;  p = -0.0076224613 + p*ww;
        p = 0.00943887047 + p*ww;  p = 1.00167406 + p*ww;
        p = 2.83297682 + p*ww;
    }
    return p * x;   // XLA f32 ErfInv: pure polynomial
}

static void compute_noise(float* noise /*64*/)
{
    float lo = nextafterf(-1.0f, 0.0f);
    float range = 1.0f - lo;    // rounds to 2.0f, matching XLA
    for (uint32_t i = 0; i < 64; ++i) {
        uint32_t o0, o1;
        threefry2x32_host(0u, 42u, 0u, i, &o0, &o1);
        uint32_t bits = o0 ^ o1;
        uint32_t fb = (bits >> 9) | 0x3f800000u;
        float f; memcpy(&f, &fb, 4);
        f -= 1.0f;
        float u = f * range + lo;
        if (u < lo) u = lo;
        double z = erfinv_host((double)u);
        noise[i] = (float)(sqrt(2.0) * z) * 0.01f;
    }
}

// ---------------------------------------------------------------------------
// Entry — inputs resolved BY SIZE
// ---------------------------------------------------------------------------
static const float* find_by_size(void* const* d_in, const int* in_sizes, int n_in,
                                 int want, int occurrence)
{
    int seen = 0;
    for (int i = 0; i < n_in; ++i) {
        if (in_sizes[i] == want) {
            if (seen == occurrence) return (const float*)d_in[i];
            ++seen;
        }
    }
    return nullptr;
}

extern "C" void kernel_launch(void* const* d_in, const int* in_sizes, int n_in,
                              void* d_out, int out_size)
{
    const float* x      = find_by_size(d_in, in_sizes, n_in, BB*CC*HW, 0);
    const float* W1     = find_by_size(d_in, in_sizes, n_in, 16384, 0);
    const float* W2     = find_by_size(d_in, in_sizes, n_in, 16384, 1);
    const float* b1     = find_by_size(d_in, in_sizes, n_in, 128, 0);
    const float* b2     = find_by_size(d_in, in_sizes, n_in, 128, 1);
    const float* W3     = find_by_size(d_in, in_sizes, n_in, 8192, 0);
    const float* b3     = find_by_size(d_in, in_sizes, n_in, 64, 0);
    const float* W4     = find_by_size(d_in, in_sizes, n_in, 4096, 0);
    const float* b4     = find_by_size(d_in, in_sizes, n_in, 64, 1);
    const float* Wu     = find_by_size(d_in, in_sizes, n_in, 512, 0);
    const float* bu     = find_by_size(d_in, in_sizes, n_in, 8, 0);
    const float* Wc     = find_by_size(d_in, in_sizes, n_in, 640, 0);
    const float* bc     = find_by_size(d_in, in_sizes, n_in, 10, 0);
    const float* conv_w = find_by_size(d_in, in_sizes, n_in, UU*CC*CC*9, 0);
    const float* conv_b = find_by_size(d_in, in_sizes, n_in, 1024, 0);
    float* out = (float*)d_out;

    if (!x || !W1 || !W2 || !b1 || !b2 || !W3 || !b3 || !W4 || !b4 ||
        !Wu || !bu || !Wc || !bc || !conv_w || !conv_b) {
        x = (const float*)d_in[0];
        W1 = (const float*)d_in[1];  b1 = (const float*)d_in[2];
        W2 = (const float*)d_in[3];  b2 = (const float*)d_in[4];
        W3 = (const float*)d_in[5];  b3 = (const float*)d_in[6];
        W4 = (const float*)d_in[7];  b4 = (const float*)d_in[8];
        Wu = (const float*)d_in[9];  bu = (const float*)d_in[10];
        Wc = (const float*)d_in[11]; bc = (const float*)d_in[12];
        conv_w = (const float*)d_in[13]; conv_b = (const float*)d_in[14];
    }

    Noise64 nz;
    compute_noise(nz.v);

    L2Args la;
    const float* l2p[12] = {W1,b1,W2,b2,W3,b3,W4,b4,Wu,bu,Wc,bc};
    const int    l2n[12] = {16384,128,16384,128,8192,64,4096,64,512,8,640,10};
    for (int i = 0; i < 12; ++i) { la.p[i] = l2p[i]; la.n[i] = l2n[i]; }

    k_stats<<<BB*CC, 128>>>(x);
    k_wsum<<<dim3(UU, 4), 288>>>(conv_w);
    k_l2<<<12, 256>>>(la);
    k_router<<<1, 128>>>(W1, b1, W2, b2, W3, b3, W4, b4,
                         Wu, bu, Wc, bc, conv_b, nz, out);
    k_weff<<<BB*CC, 128>>>(conv_w, conv_b);
    k_conv<<<512, 256>>>(x, out);
}

// round 13
// speedup vs baseline: 3.9845x; 2.9549x over previous
#include <cuda_runtime.h>
#include <cuda_bf16.h>
#include <math.h>
#include <string.h>
#include <stdint.h>

// ---------------------------------------------------------------------------
// Problem constants
// ---------------------------------------------------------------------------
#define BB 8
#define CC 128
#define HH 64
#define WW 64
#define UU 8
#define TOPK 2
#define LL 10
#define HID 128

#define HW (HH*WW)                       // 4096
#define N_FINAL (BB*CC*HW)               // 4194304
#define OFF_CLS  (N_FINAL)
#define OFF_L2   (N_FINAL + 80)
#define OFF_TOPI (N_FINAL + 81)
#define OFF_LB   (N_FINAL + 97)

#define KTOT 1152                        // 128 ci * 9

// ---------------------------------------------------------------------------
// Device scratch
// ---------------------------------------------------------------------------
__device__ float g_stats[BB*CC*9];
__device__ float g_wsum[UU*CC*9];
__device__ float g_norms[12];
__device__ int   g_topi[BB*2];
__device__ float g_gate[BB*UU];
__device__ float g_beff[BB*CC];
__device__ float g_Weff[BB*CC*KTOT];     // 4.72 MB, [b][co][k] k-major

// TF32 rounding
__device__ __forceinline__ float tf32r(float v)
{
    uint32_t r;
    asm("cvt.rna.tf32.f32 %0, %1;" : "=r"(r) : "f"(v));
    float f;
    asm("mov.b32 %0, %1;" : "=f"(f) : "r"(r));
    return f;
}

// portable warp-level tf32 MMA (sm_80+): D(16x8) += A(16x8) * B(8x8)
__device__ __forceinline__ void mma168(float* d, const uint32_t* a, const uint32_t* bf)
{
    asm volatile(
        "mma.sync.aligned.m16n8k8.row.col.f32.tf32.tf32.f32 "
        "{%0,%1,%2,%3}, {%4,%5,%6,%7}, {%8,%9}, {%0,%1,%2,%3};"
        : "+f"(d[0]), "+f"(d[1]), "+f"(d[2]), "+f"(d[3])
        : "r"(a[0]), "r"(a[1]), "r"(a[2]), "r"(a[3]), "r"(bf[0]), "r"(bf[1]));
}

// ---------------------------------------------------------------------------
// K1 (fused pre-pass): [0,1024) stats; [1024,1064) wsum; [1064,1076) l2
// ---------------------------------------------------------------------------
struct L2Args { const float* p[12]; int n[12]; };

__global__ void __launch_bounds__(256) k_pre(const float* __restrict__ x,
                                             const float* __restrict__ conv_w,
                                             L2Args a)
{
    int blk = blockIdx.x;
    int t   = threadIdx.x;

    if (blk < 1024) {
        const float* base = x + (size_t)blk * HW;
        float T=0.f, r0=0.f, r63=0.f, c0=0.f, c63=0.f;
        for (int i = t; i < HW; i += 256) {
            float v = base[i];
            int y = i >> 6, xc = i & 63;
            T += v;
            if (y == 0)   r0  += v;
            if (y == 63)  r63 += v;
            if (xc == 0)  c0  += v;
            if (xc == 63) c63 += v;
        }
        #pragma unroll
        for (int off = 16; off; off >>= 1) {
            T   += __shfl_down_sync(0xffffffffu, T,   off);
            r0  += __shfl_down_sync(0xffffffffu, r0,  off);
            r63 += __shfl_down_sync(0xffffffffu, r63, off);
            c0  += __shfl_down_sync(0xffffffffu, c0,  off);
            c63 += __shfl_down_sync(0xffffffffu, c63, off);
        }
        __shared__ float red[8][5];
        if ((t & 31) == 0) {
            int w = t >> 5;
            red[w][0]=T; red[w][1]=r0; red[w][2]=r63; red[w][3]=c0; red[w][4]=c63;
        }
        __syncthreads();
        if (t == 0) {
            float s[5] = {0,0,0,0,0};
            for (int w = 0; w < 8; ++w)
                for (int k = 0; k < 5; ++k) s[k] += red[w][k];
            float* o = g_stats + (size_t)blk * 9;
            o[0]=s[0]; o[1]=s[1]; o[2]=s[2]; o[3]=s[3]; o[4]=s[4];
            o[5]=base[0]; o[6]=base[63]; o[7]=base[63*64]; o[8]=base[HW-1];
        }
    } else if (blk < 1064) {
        int q = blk - 1024;
        int u = q / 5;
        int idx = (q % 5) * 256 + t;
        if (idx < KTOT) {
            const float* base = conv_w + (size_t)u * CC * KTOT + idx;
            float s = 0.f;
            for (int co = 0; co < CC; ++co) s += base[(size_t)co * KTOT];
            g_wsum[u * KTOT + idx] = s;
        }
    } else {
        int bi = blk - 1064;
        const float* p = a.p[bi]; int n = a.n[bi];
        float s = 0.f;
        for (int i = t; i < n; i += 256) { float v = p[i]; s += v*v; }
        #pragma unroll
        for (int off = 16; off; off >>= 1) s += __shfl_down_sync(0xffffffffu, s, off);
        __shared__ float ws[8];
        if ((t & 31) == 0) ws[t >> 5] = s;
        __syncthreads();
        if (t == 0) {
            float tot = 0.f;
            for (int w = 0; w < 8; ++w) tot += ws[w];
            g_norms[bi] = sqrtf(tot);
        }
    }
}

// ---------------------------------------------------------------------------
// K2: router (1 block, 128 thr)
// ---------------------------------------------------------------------------
struct Noise64 { float v[64]; };

__global__ void k_router(const float* __restrict__ W1, const float* __restrict__ b1,
                         const float* __restrict__ W2, const float* __restrict__ b2,
                         const float* __restrict__ W3, const float* __restrict__ b3,
                         const float* __restrict__ W4, const float* __restrict__ b4,
                         const float* __restrict__ Wu, const float* __restrict__ bu,
                         const float* __restrict__ Wc, const float* __restrict__ bc,
                         const float* __restrict__ conv_b,
                         Noise64 nz, float* __restrict__ out)
{
    __shared__ float A[BB][HID];
    __shared__ float Bv[BB][HID];
    __shared__ float F[BB][64];
    __shared__ float S[BB][UU];
    __shared__ int   TI[BB][2];
    __shared__ float bsum_s[UU];
    __shared__ float m_s[BB][UU];
    __shared__ float part[16][128];
    __shared__ float wu_s[512];
    __shared__ float wc_s[640];
    __shared__ float cb_s[1024];

    int t = threadIdx.x;   // 128

    for (int i = t; i < 512;  i += 128) wu_s[i] = Wu[i];
    for (int i = t; i < 640;  i += 128) wc_s[i] = Wc[i];
    for (int i = t; i < 1024; i += 128) cb_s[i] = conv_b[i];
    for (int b = 0; b < BB; ++b)
        A[b][t] = g_stats[(size_t)(b*CC + t) * 9] * (1.0f/4096.0f);
    __syncthreads();

    // L1
    {
        const float4* Wv = (const float4*)W1;
        float acc[BB]; float bb = b1[t];
        #pragma unroll
        for (int b = 0; b < BB; ++b) acc[b] = bb;
        #pragma unroll 4
        for (int i = 0; i < 32; ++i) {
            float4 w = Wv[t*32 + i];
            int c = i*4;
            #pragma unroll
            for (int b = 0; b < BB; ++b) {
                acc[b] = fmaf(A[b][c+0], w.x, acc[b]);
                acc[b] = fmaf(A[b][c+1], w.y, acc[b]);
                acc[b] = fmaf(A[b][c+2], w.z, acc[b]);
                acc[b] = fmaf(A[b][c+3], w.w, acc[b]);
            }
        }
        #pragma unroll
        for (int b = 0; b < BB; ++b) Bv[b][t] = fmaxf(acc[b], 0.f);
    }
    __syncthreads();
    // L2
    {
        const float4* Wv = (const float4*)W2;
        float acc[BB]; float bb = b2[t];
        #pragma unroll
        for (int b = 0; b < BB; ++b) acc[b] = bb;
        #pragma unroll 4
        for (int i = 0; i < 32; ++i) {
            float4 w = Wv[t*32 + i];
            int c = i*4;
            #pragma unroll
            for (int b = 0; b < BB; ++b) {
                acc[b] = fmaf(Bv[b][c+0], w.x, acc[b]);
                acc[b] = fmaf(Bv[b][c+1], w.y, acc[b]);
                acc[b] = fmaf(Bv[b][c+2], w.z, acc[b]);
                acc[b] = fmaf(Bv[b][c+3], w.w, acc[b]);
            }
        }
        #pragma unroll
        for (int b = 0; b < BB; ++b) A[b][t] = fmaxf(acc[b], 0.f);
    }
    __syncthreads();
    // L3: 128 -> 64
    if (t < 64) {
        const float4* Wv = (const float4*)W3;
        float acc[BB]; float bb = b3[t];
        #pragma unroll
        for (int b = 0; b < BB; ++b) acc[b] = bb;
        #pragma unroll 4
        for (int i = 0; i < 32; ++i) {
            float4 w = Wv[t*32 + i];
            int c = i*4;
            #pragma unroll
            for (int b = 0; b < BB; ++b) {
                acc[b] = fmaf(A[b][c+0], w.x, acc[b]);
                acc[b] = fmaf(A[b][c+1], w.y, acc[b]);
                acc[b] = fmaf(A[b][c+2], w.z, acc[b]);
                acc[b] = fmaf(A[b][c+3], w.w, acc[b]);
            }
        }
        #pragma unroll
        for (int b = 0; b < BB; ++b) Bv[b][t] = fmaxf(acc[b], 0.f);
    }
    __syncthreads();
    // L4: 64 -> 64 (no relu)
    if (t < 64) {
        const float4* Wv = (const float4*)W4;
        float acc[BB]; float bb = b4[t];
        #pragma unroll
        for (int b = 0; b < BB; ++b) acc[b] = bb;
        #pragma unroll 4
        for (int i = 0; i < 16; ++i) {
            float4 w = Wv[t*16 + i];
            int c = i*4;
            #pragma unroll
            for (int b = 0; b < BB; ++b) {
                acc[b] = fmaf(Bv[b][c+0], w.x, acc[b]);
                acc[b] = fmaf(Bv[b][c+1], w.y, acc[b]);
                acc[b] = fmaf(Bv[b][c+2], w.z, acc[b]);
                acc[b] = fmaf(Bv[b][c+3], w.w, acc[b]);
            }
        }
        #pragma unroll
        for (int b = 0; b < BB; ++b) F[b][t] = acc[b];
    }
    __syncthreads();

    if (t < BB*UU) {
        int b = t >> 3, u = t & 7;
        float a = bu[u] + nz.v[t];
        for (int c = 0; c < 64; ++c) a = fmaf(F[b][c], wu_s[u*64 + c], a);
        S[b][u] = a;
    }
    if (t < BB*LL) {
        int b = t / LL, l = t % LL;
        float a = bc[l];
        for (int c = 0; c < 64; ++c) a = fmaf(F[b][c], wc_s[l*64 + c], a);
        out[OFF_CLS + t] = a;
    }
    if (t >= 96 && t < 96 + UU) {
        int u = t - 96;
        float s = 0.f;
        for (int c = 0; c < CC; ++c) s += cb_s[u*CC + c];
        bsum_s[u] = s;
    }
    __syncthreads();

    if (t < BB) {
        int b = t;
        int i0 = 0; float v0 = S[b][0];
        for (int u = 1; u < UU; ++u) if (S[b][u] > v0) { v0 = S[b][u]; i0 = u; }
        int i1 = -1; float v1 = -3.4e38f;
        for (int u = 0; u < UU; ++u) if (u != i0 && S[b][u] > v1) { v1 = S[b][u]; i1 = u; }
        TI[b][0] = i0;  TI[b][1] = i1;
        g_topi[b*2] = i0;  g_topi[b*2+1] = i1;
        out[OFF_TOPI + b*2]     = (float)i0;
        out[OFF_TOPI + b*2 + 1] = (float)i1;
    }
    __syncthreads();

    if (t == 0) {
        int cnt[UU] = {0,0,0,0,0,0,0,0};
        for (int b = 0; b < BB; ++b) { cnt[TI[b][0]]++; cnt[TI[b][1]]++; }
        float lb = 0.f;
        for (int u = 0; u < UU; ++u) {
            float d = (float)cnt[u] * (1.0f/16.0f) - 0.125f;
            lb += d*d;
        }
        out[OFF_LB] = lb * (1.0f/8.0f);
        float s = 0.f;
        for (int i = 0; i < 12; ++i) s += g_norms[i];
        out[OFF_L2] = 0.01f * s;
    }
    if (t < BB*UU) m_s[t>>3][t&7] = bsum_s[t&7] * (1.0f/128.0f);

    // analytic window sums, sync-free partials, thread t = ci
    for (int b = 0; b < BB; ++b) {
        const float* st = g_stats + (size_t)(b*CC + t) * 9;
        float T  = st[0], R0 = st[1], R63 = st[2], C0 = st[3], C63 = st[4];
        float x00 = st[5], x0e = st[6], xe0 = st[7], xee = st[8];
        float Sv[9];
        #pragma unroll
        for (int dy = 0; dy < 3; ++dy)
            #pragma unroll
            for (int dx = 0; dx < 3; ++dx) {
                float s = T;
                if (dy == 0) s -= R63;
                if (dy == 2) s -= R0;
                if (dx == 0) s -= C63;
                if (dx == 2) s -= C0;
                if (dy == 0 && dx == 0) s += xee;
                if (dy == 0 && dx == 2) s += xe0;
                if (dy == 2 && dx == 0) s += x0e;
                if (dy == 2 && dx == 2) s += x00;
                Sv[dy*3 + dx] = s;
            }
        #pragma unroll
        for (int j = 0; j < 2; ++j) {
            int u = TI[b][j];
            const float* wr = g_wsum + (size_t)u * KTOT + t*9;
            float p = 0.f;
            #pragma unroll
            for (int k = 0; k < 9; ++k) p = fmaf(wr[k], Sv[k], p);
            part[b*2 + j][t] = p;
        }
    }
    __syncthreads();

    {
        int w = t >> 5, l = t & 31;
        #pragma unroll
        for (int q = 0; q < 4; ++q) {
            int pr = w*4 + q;
            float s = part[pr][l] + part[pr][l+32] + part[pr][l+64] + part[pr][l+96];
            #pragma unroll
            for (int off = 16; off; off >>= 1) s += __shfl_down_sync(0xffffffffu, s, off);
            if (l == 0) {
                int bb2 = pr >> 1, jj = pr & 1;
                int u = TI[bb2][jj];
                m_s[bb2][u] += s * (1.0f/524288.0f);
            }
        }
    }
    __syncthreads();

    if (t < BB) {
        int b = t;
        float mx = -3.4e38f;
        for (int u = 0; u < UU; ++u) mx = fmaxf(mx, m_s[b][u]);
        float e[UU], s = 0.f;
        for (int u = 0; u < UU; ++u) { e[u] = expf(m_s[b][u] - mx); s += e[u]; }
        for (int u = 0; u < UU; ++u) g_gate[b*UU + u] = e[u] / s;
    }
}

// ---------------------------------------------------------------------------
// K3: W_eff (tf32-rounded per unit, gated) k-major + b_eff. grid 1024, 128 thr
// ---------------------------------------------------------------------------
__global__ void k_weff(const float* __restrict__ conv_w, const float* __restrict__ conv_b)
{
    int b  = blockIdx.x >> 7;
    int co = blockIdx.x & 127;
    int t  = threadIdx.x;          // 128
    int u0 = g_topi[b*2], u1 = g_topi[b*2+1];
    float g0 = g_gate[b*UU + u0], g1 = g_gate[b*UU + u1];
    const float* w0 = conv_w + (size_t)(u0*CC + co) * KTOT;
    const float* w1 = conv_w + (size_t)(u1*CC + co) * KTOT;
    float* dst = g_Weff + (size_t)(b*CC + co) * KTOT;
    #pragma unroll
    for (int j = 0; j < 9; ++j) {
        int k = j*128 + t;
        dst[k] = tf32r(g0 * tf32r(w0[k]) + g1 * tf32r(w1[k]));
    }
    if (t == 0) {
        float s = 0.f;
        for (int u = 0; u < UU; ++u) s += g_gate[b*UU + u] * conv_b[u*CC + co];
        g_beff[b*CC + co] = s;
    }
}

// ---------------------------------------------------------------------------
// K4: tf32 mma.sync implicit-GEMM conv
// grid 256 = 8 b x 32 tiles (128 px = 2 rows); 256 thr = 8 warps (2m x 4n)
// D[128co x 128px] = Weff[128 x 1152] * im2col[128 x 1152]^T
// ---------------------------------------------------------------------------
__global__ void __launch_bounds__(256) k_conv_mma(const float* __restrict__ xg,
                                                  float* __restrict__ out)
{
    __shared__ float As[128*36];      // A chunk: 128co x 32k, stride 36
    __shared__ float Bs[128*36];      // B chunk: 128px x 32k, stride 36

    int tid  = threadIdx.x;
    int lane = tid & 31, wid = tid >> 5;
    int b    = blockIdx.x >> 5;
    int tile = blockIdx.x & 31;
    int warp_m = wid >> 2;            // 0..1 (64 co each)
    int warp_n = wid & 3;             // 0..3 (32 px each)
    int gid = lane >> 2, tig = lane & 3;

    const float* xb = xg + (size_t)b * (CC*HW);
    const float* Wb = g_Weff + (size_t)b * (CC*KTOT);

    int n  = tid & 127;               // pixel this thread builds
    int kh = tid >> 7;                // which 16-k half
    int py = tile*2 + (n >> 6);
    int px = n & 63;

    float d[16][4];
    #pragma unroll
    for (int i = 0; i < 16; ++i)
        #pragma unroll
        for (int j = 0; j < 4; ++j) d[i][j] = 0.f;

    #pragma unroll 1
    for (int c = 0; c < 36; ++c) {
        __syncthreads();
        // A: 128co x 32k coalesced load (1024 float4, 4 per thread)
        #pragma unroll
        for (int i = 0; i < 4; ++i) {
            int e  = tid + i*256;
            int co = e >> 3;
            int kq = (e & 7) * 4;
            float4 v = *(const float4*)(Wb + (size_t)co*KTOT + c*32 + kq);
            *(float4*)(As + co*36 + kq) = v;
        }
        // B: im2col 32 k-values for 128 pixels
        {
            int kbase = c*32 + kh*16;
            #pragma unroll
            for (int g = 0; g < 4; ++g) {
                float v[4];
                #pragma unroll
                for (int jj = 0; jj < 4; ++jj) {
                    int k  = kbase + g*4 + jj;
                    int ci = (k * 7282) >> 16;      // k/9
                    int r  = k - ci*9;
                    int dy = r / 3 - 1;
                    int dx = r - (r/3)*3 - 1;
                    int yy = py + dy, xx = px + dx;
                    float val = 0.f;
                    if ((unsigned)yy < 64u && (unsigned)xx < 64u)
                        val = xb[((size_t)ci << 12) + (yy << 6) + xx];
                    v[jj] = tf32r(val);
                }
                *(float4*)(Bs + n*36 + kh*16 + g*4) = make_float4(v[0], v[1], v[2], v[3]);
            }
        }
        __syncthreads();

        #pragma unroll
        for (int ks = 0; ks < 4; ++ks) {
            uint32_t af[4][4];
            #pragma unroll
            for (int mt = 0; mt < 4; ++mt) {
                int row = warp_m*64 + mt*16 + gid;
                int col = ks*8 + tig;
                af[mt][0] = __float_as_uint(As[row*36 + col]);
                af[mt][1] = __float_as_uint(As[(row+8)*36 + col]);
                af[mt][2] = __float_as_uint(As[row*36 + col + 4]);
                af[mt][3] = __float_as_uint(As[(row+8)*36 + col + 4]);
            }
            uint32_t bf[4][2];
            #pragma unroll
            for (int nt = 0; nt < 4; ++nt) {
                int nn = warp_n*32 + nt*8 + gid;
                int kk = ks*8 + tig;
                bf[nt][0] = __float_as_uint(Bs[nn*36 + kk]);
                bf[nt][1] = __float_as_uint(Bs[nn*36 + kk + 4]);
            }
            #pragma unroll
            for (int mt = 0; mt < 4; ++mt)
                #pragma unroll
                for (int nt = 0; nt < 4; ++nt)
                    mma168(d[mt*4 + nt], af[mt], bf[nt]);
        }
    }

    // epilogue: + b_eff, write (c-frag layout: rows gid/gid+8, cols 2*tig/+1)
    #pragma unroll
    for (int mt = 0; mt < 4; ++mt) {
        int co = warp_m*64 + mt*16 + gid;
        float be0 = g_beff[b*CC + co];
        float be8 = g_beff[b*CC + co + 8];
        #pragma unroll
        for (int nt = 0; nt < 4; ++nt) {
            int col = warp_n*32 + nt*8 + tig*2;
            float* op = out + (size_t)(b*CC + co) * HW + tile*128 + col;
            *(float2*)op = make_float2(d[mt*4+nt][0] + be0, d[mt*4+nt][1] + be0);
            *(float2*)(op + 8*HW) = make_float2(d[mt*4+nt][2] + be8, d[mt*4+nt][3] + be8);
        }
    }
}

// ---------------------------------------------------------------------------
// Host: JAX threefry2x32 noise (partitionable), key(42)
// ---------------------------------------------------------------------------
static inline uint32_t rotl32(uint32_t x, int d) { return (x << d) | (x >> (32 - d)); }

static void threefry2x32_host(uint32_t k0, uint32_t k1, uint32_t x0, uint32_t x1,
                              uint32_t* o0, uint32_t* o1)
{
    const uint32_t ks0 = k0, ks1 = k1, ks2 = k0 ^ k1 ^ 0x1BD11BDAu;
    const int ra[4] = {13, 15, 26, 6};
    const int rb[4] = {17, 29, 16, 24};
    x0 += ks0; x1 += ks1;
    for (int i = 0; i < 4; ++i) { x0 += x1; x1 = rotl32(x1, ra[i]); x1 ^= x0; }
    x0 += ks1; x1 += ks2 + 1u;
    for (int i = 0; i < 4; ++i) { x0 += x1; x1 = rotl32(x1, rb[i]); x1 ^= x0; }
    x0 += ks2; x1 += ks0 + 2u;
    for (int i = 0; i < 4; ++i) { x0 += x1; x1 = rotl32(x1, ra[i]); x1 ^= x0; }
    x0 += ks0; x1 += ks1 + 3u;
    for (int i = 0; i < 4; ++i) { x0 += x1; x1 = rotl32(x1, rb[i]); x1 ^= x0; }
    x0 += ks1; x1 += ks2 + 4u;
    for (int i = 0; i < 4; ++i) { x0 += x1; x1 = rotl32(x1, ra[i]); x1 ^= x0; }
    x0 += ks2; x1 += ks0 + 5u;
    *o0 = x0; *o1 = x1;
}

static double erfinv_host(double x)
{
    double p;
    double ww = -log((1.0 - x) * (1.0 + x));
    if (ww < 5.0) {
        ww -= 2.5;
        p = 2.81022636e-08;        p = 3.43273939e-07 + p*ww;
        p = -3.5233877e-06 + p*ww; p = -4.39150654e-06 + p*ww;
        p = 0.00021858087 + p*ww;  p = -0.00125372503 + p*ww;
        p = -0.00417768164 + p*ww; p = 0.246640727 + p*ww;
        p = 1.50140941 + p*ww;
    } else {
        ww = sqrt(ww) - 3.0;
        p = -0.000200214257;       p = 0.000100950558 + p*ww;
        p = 0.00134934322 + p*ww;  p = -0.00367342844 + p*ww;
        p = 0.00573950773 + p*ww;  p = -0.0076224613 + p*ww;
        p = 0.00943887047 + p*ww;  p = 1.00167406 + p*ww;
        p = 2.83297682 + p*ww;
    }
    return p * x;
}

static void compute_noise(float* noise /*64*/)
{
    float lo = nextafterf(-1.0f, 0.0f);
    float range = 1.0f - lo;
    for (uint32_t i = 0; i < 64; ++i) {
        uint32_t o0, o1;
        threefry2x32_host(0u, 42u, 0u, i, &o0, &o1);
        uint32_t bits = o0 ^ o1;
        uint32_t fb = (bits >> 9) | 0x3f800000u;
        float f; memcpy(&f, &fb, 4);
        f -= 1.0f;
        float u = f * range + lo;
        if (u < lo) u = lo;
        double z = erfinv_host((double)u);
        noise[i] = (float)(sqrt(2.0) * z) * 0.01f;
    }
}

// ---------------------------------------------------------------------------
// Entry — inputs resolved BY SIZE
// ---------------------------------------------------------------------------
static const float* find_by_size(void* const* d_in, const int* in_sizes, int n_in,
                                 int want, int occurrence)
{
    int seen = 0;
    for (int i = 0; i < n_in; ++i) {
        if (in_sizes[i] == want) {
            if (seen == occurrence) return (const float*)d_in[i];
            ++seen;
        }
    }
    return nullptr;
}

extern "C" void kernel_launch(void* const* d_in, const int* in_sizes, int n_in,
                              void* d_out, int out_size)
{
    const float* x      = find_by_size(d_in, in_sizes, n_in, BB*CC*HW, 0);
    const float* W1     = find_by_size(d_in, in_sizes, n_in, 16384, 0);
    const float* W2     = find_by_size(d_in, in_sizes, n_in, 16384, 1);
    const float* b1     = find_by_size(d_in, in_sizes, n_in, 128, 0);
    const float* b2     = find_by_size(d_in, in_sizes, n_in, 128, 1);
    const float* W3     = find_by_size(d_in, in_sizes, n_in, 8192, 0);
    const float* b3     = find_by_size(d_in, in_sizes, n_in, 64, 0);
    const float* W4     = find_by_size(d_in, in_sizes, n_in, 4096, 0);
    const float* b4     = find_by_size(d_in, in_sizes, n_in, 64, 1);
    const float* Wu     = find_by_size(d_in, in_sizes, n_in, 512, 0);
    const float* bu     = find_by_size(d_in, in_sizes, n_in, 8, 0);
    const float* Wc     = find_by_size(d_in, in_sizes, n_in, 640, 0);
    const float* bc     = find_by_size(d_in, in_sizes, n_in, 10, 0);
    const float* conv_w = find_by_size(d_in, in_sizes, n_in, UU*CC*CC*9, 0);
    const float* conv_b = find_by_size(d_in, in_sizes, n_in, 1024, 0);
    float* out = (float*)d_out;

    if (!x || !W1 || !W2 || !b1 || !b2 || !W3 || !b3 || !W4 || !b4 ||
        !Wu || !bu || !Wc || !bc || !conv_w || !conv_b) {
        x = (const float*)d_in[0];
        W1 = (const float*)d_in[1];  b1 = (const float*)d_in[2];
        W2 = (const float*)d_in[3];  b2 = (const float*)d_in[4];
        W3 = (const float*)d_in[5];  b3 = (const float*)d_in[6];
        W4 = (const float*)d_in[7];  b4 = (const float*)d_in[8];
        Wu = (const float*)d_in[9];  bu = (const float*)d_in[10];
        Wc = (const float*)d_in[11]; bc = (const float*)d_in[12];
        conv_w = (const float*)d_in[13]; conv_b = (const float*)d_in[14];
    }

    Noise64 nz;
    compute_noise(nz.v);

    L2Args la;
    const float* l2p[12] = {W1,b1,W2,b2,W3,b3,W4,b4,Wu,bu,Wc,bc};
    const int    l2n[12] = {16384,128,16384,128,8192,64,4096,64,512,8,640,10};
    for (int i = 0; i < 12; ++i) { la.p[i] = l2p[i]; la.n[i] = l2n[i]; }

    k_pre<<<1076, 256>>>(x, conv_w, la);
    k_router<<<1, 128>>>(W1, b1, W2, b2, W3, b3, W4, b4,
                         Wu, bu, Wc, bc, conv_b, nz, out);
    k_weff<<<1024, 128>>>(conv_w, conv_b);
    k_conv_mma<<<256, 256>>>(x, out);
}